// round 8
// baseline (speedup 1.0000x reference)
#include <cuda_runtime.h>
#include <cuda_fp16.h>

// Problem constants (fixed by the reference)
#define N_NODES 20000
#define N_EDGES 200000
#define N_SEG   16
#define EXTENT  32
#define N_PATHS 64
#define OP_SIZE (N_SEG * EXTENT)   // 512
#define EPB     8                  // edges per block (200000 % 8 == 0)

// Path metadata sorted by output segment (i3).
__device__ int4 g_meta[N_PATHS];
__device__ int  g_seg_start[N_SEG + 1];

// Counting-sort state: histogram/cursor per node, sorted edge order.
__device__ int g_hist[N_NODES];
__device__ int g_order[N_EDGES];

// ---------------------------------------------------------------------------
// Prep 1: zero node histogram + counting-sort the 64 paths by output segment.
__global__ void prep_zero_paths_kernel(const int* __restrict__ path_indices,
                                       const float* __restrict__ path_coeffs) {
    const int i = blockIdx.x * blockDim.x + threadIdx.x;
    if (i < N_NODES) g_hist[i] = 0;

    if (blockIdx.x == 0 && threadIdx.x == 0) {
        int cnt[N_SEG];
#pragma unroll
        for (int s = 0; s < N_SEG; s++) cnt[s] = 0;
        for (int p = 0; p < N_PATHS; p++) cnt[path_indices[p * 3 + 2]]++;
        int start[N_SEG + 1];
        start[0] = 0;
#pragma unroll
        for (int s = 0; s < N_SEG; s++) start[s + 1] = start[s] + cnt[s];
        for (int s = 0; s <= N_SEG; s++) g_seg_start[s] = start[s];
        int pos[N_SEG];
#pragma unroll
        for (int s = 0; s < N_SEG; s++) pos[s] = start[s];
        for (int p = 0; p < N_PATHS; p++) {
            int s   = path_indices[p * 3 + 2];
            int idx = pos[s]++;
            int4 m;
            m.x = path_indices[p * 3 + 0] * (EXTENT * EPB * 2);  // smem bytes
            m.y = path_indices[p * 3 + 1] * (EXTENT * EPB * 2);
            m.z = __float_as_int(path_coeffs[p]);
            m.w = 0;
            g_meta[idx] = m;
        }
    }
}

// Prep 2: histogram of dst.
__global__ void prep_hist_kernel(const int* __restrict__ dst) {
    const int e = blockIdx.x * blockDim.x + threadIdx.x;
    if (e < N_EDGES) atomicAdd(&g_hist[dst[e]], 1);
}

// Prep 3: single-block exclusive scan of g_hist (20000 elems), in place:
// afterwards g_hist[i] = start offset of node i's bin (used as scatter cursor).
#define SCAN_T 1024
#define SCAN_C 20   // 1024*20 = 20480 >= 20000
__global__ void prep_scan_kernel() {
    __shared__ int part[SCAN_T];
    const int t = threadIdx.x;
    const int base = t * SCAN_C;
    int local[SCAN_C];
    int s = 0;
#pragma unroll
    for (int i = 0; i < SCAN_C; i++) {
        const int idx = base + i;
        const int v = (idx < N_NODES) ? g_hist[idx] : 0;
        local[i] = v;
        s += v;
    }
    part[t] = s;
    __syncthreads();
    // Hillis-Steele inclusive scan over the 1024 partials.
    for (int off = 1; off < SCAN_T; off <<= 1) {
        const int v   = part[t];
        const int add = (t >= off) ? part[t - off] : 0;
        __syncthreads();
        part[t] = v + add;
        __syncthreads();
    }
    int run = (t == 0) ? 0 : part[t - 1];   // exclusive prefix for this chunk
#pragma unroll
    for (int i = 0; i < SCAN_C; i++) {
        const int idx = base + i;
        if (idx < N_NODES) g_hist[idx] = run;
        run += local[i];
    }
}

// Prep 4: scatter edge ids into dst-sorted order.
__global__ void prep_scatter_kernel(const int* __restrict__ dst) {
    const int e = blockIdx.x * blockDim.x + threadIdx.x;
    if (e < N_EDGES) {
        const int pos = atomicAdd(&g_hist[dst[e]], 1);
        g_order[pos] = e;
    }
}

// ---------------------------------------------------------------------------
// Main: 8 dst-sorted edges per block, f16 tiles transposed to [pos][edge].
// One LDS.128 fetches all 8 edges' values for a (seg,lane) position.
// Same-dst accumulators merged in-register -> ~1.8 atomics/block instead of 8.
__global__ __launch_bounds__(OP_SIZE, 3)
void seg_poly_kernel(const float* __restrict__ x_nodes,
                     const float* __restrict__ x_edges,
                     const int* __restrict__ src,
                     const int* __restrict__ dst,
                     float* __restrict__ out) {
    __shared__ __align__(16) __half s_x1[OP_SIZE * EPB];  // 8 KB
    __shared__ __align__(16) __half s_x2[OP_SIZE * EPB];  // 8 KB
    __shared__ int4 s_meta[N_PATHS];
    __shared__ int  s_start[N_SEG + 1];
    __shared__ int  s_e[EPB];
    __shared__ int  s_src[EPB];
    __shared__ int  s_dst[EPB];

    const int t = threadIdx.x;

    if (t < EPB) {
        const int e = g_order[blockIdx.x * EPB + t];
        s_e[t]   = e;
        s_src[t] = src[e];
        s_dst[t] = dst[e];
    }
    if (t < N_PATHS) s_meta[t] = g_meta[t];
    if (t >= N_PATHS && t < N_PATHS + N_SEG + 1) s_start[t - N_PATHS] = g_seg_start[t - N_PATHS];
    __syncthreads();

    // Stage x_edges: thread t owns position t; gather from the 8 (permuted)
    // edge rows -- each LDG coalesced in-warp, 8 independent loads (MLP 8).
    {
        float v[EPB];
#pragma unroll
        for (int k = 0; k < EPB; k++)
            v[k] = x_edges[(size_t)s_e[k] * OP_SIZE + t];
        __half2 h0 = __floats2half2_rn(v[0], v[1]);
        __half2 h1 = __floats2half2_rn(v[2], v[3]);
        __half2 h2 = __floats2half2_rn(v[4], v[5]);
        __half2 h3 = __floats2half2_rn(v[6], v[7]);
        uint4 pk;
        pk.x = *(const unsigned*)&h0; pk.y = *(const unsigned*)&h1;
        pk.z = *(const unsigned*)&h2; pk.w = *(const unsigned*)&h3;
        ((uint4*)s_x2)[t] = pk;   // addr = t*16 -> conflict-free
    }
    // Stage x_nodes rows src[e_k] the same way.
    {
        float v[EPB];
#pragma unroll
        for (int k = 0; k < EPB; k++)
            v[k] = x_nodes[(size_t)s_src[k] * OP_SIZE + t];
        __half2 h0 = __floats2half2_rn(v[0], v[1]);
        __half2 h1 = __floats2half2_rn(v[2], v[3]);
        __half2 h2 = __floats2half2_rn(v[4], v[5]);
        __half2 h3 = __floats2half2_rn(v[6], v[7]);
        uint4 pk;
        pk.x = *(const unsigned*)&h0; pk.y = *(const unsigned*)&h1;
        pk.z = *(const unsigned*)&h2; pk.w = *(const unsigned*)&h3;
        ((uint4*)s_x1)[t] = pk;
    }
    __syncthreads();

    const int lane = t & 31;
    const int j0 = s_start[t >> 5];
    const int j1 = s_start[(t >> 5) + 1];

    const char* b1 = (const char*)s_x1 + lane * (EPB * 2);
    const char* b2 = (const char*)s_x2 + lane * (EPB * 2);

    float a[EPB];
#pragma unroll
    for (int k = 0; k < EPB; k++) a[k] = 0.f;

    for (int j = j0; j < j1; j++) {
        const int4 m = s_meta[j];                       // LDS.128, warp-uniform
        const float c = __int_as_float(m.z);
        const uint4 w1 = *(const uint4*)(b1 + m.x);     // LDS.128: 8 edges (x1)
        const uint4 w2 = *(const uint4*)(b2 + m.y);     // LDS.128: 8 edges (x2)
        const __half2 p0 = __hmul2(*(const __half2*)&w1.x, *(const __half2*)&w2.x);
        const __half2 p1 = __hmul2(*(const __half2*)&w1.y, *(const __half2*)&w2.y);
        const __half2 p2 = __hmul2(*(const __half2*)&w1.z, *(const __half2*)&w2.z);
        const __half2 p3 = __hmul2(*(const __half2*)&w1.w, *(const __half2*)&w2.w);
        const float2 f0 = __half22float2(p0);
        const float2 f1 = __half22float2(p1);
        const float2 f2 = __half22float2(p2);
        const float2 f3 = __half22float2(p3);
        a[0] = fmaf(c, f0.x, a[0]);  a[1] = fmaf(c, f0.y, a[1]);
        a[2] = fmaf(c, f1.x, a[2]);  a[3] = fmaf(c, f1.y, a[3]);
        a[4] = fmaf(c, f2.x, a[4]);  a[5] = fmaf(c, f2.y, a[5]);
        a[6] = fmaf(c, f3.x, a[6]);  a[7] = fmaf(c, f3.y, a[7]);
    }

    if (j1 > j0) {
        // dsts are non-decreasing within the block: merge equal-dst runs in
        // registers, one no-return atomic per distinct dst (block-uniform
        // branches -> no divergence).
        float carry = a[EPB - 1];
#pragma unroll
        for (int k = EPB - 1; k >= 1; k--) {
            if (s_dst[k] != s_dst[k - 1]) {
                atomicAdd(&out[(size_t)s_dst[k] * OP_SIZE + t], carry);
                carry = a[k - 1];
            } else {
                carry += a[k - 1];
            }
        }
        atomicAdd(&out[(size_t)s_dst[0] * OP_SIZE + t], carry);
    }
    // Segments with no paths contribute exactly 0 -> output stays at memset 0.
}

extern "C" void kernel_launch(void* const* d_in, const int* in_sizes, int n_in,
                              void* d_out, int out_size) {
    const float* x_nodes      = (const float*)d_in[0];
    const float* x_edges      = (const float*)d_in[1];
    const float* path_coeffs  = (const float*)d_in[2];
    const int*   src          = (const int*)d_in[3];
    const int*   dst          = (const int*)d_in[4];
    const int*   path_indices = (const int*)d_in[5];
    float* out = (float*)d_out;

    // Output is poisoned 0xAA by the harness; zero it (graph-capturable).
    cudaMemsetAsync(out, 0, (size_t)N_NODES * OP_SIZE * sizeof(float));

    prep_zero_paths_kernel<<<(N_NODES + 511) / 512, 512>>>(path_indices, path_coeffs);
    prep_hist_kernel<<<(N_EDGES + 511) / 512, 512>>>(dst);
    prep_scan_kernel<<<1, SCAN_T>>>();
    prep_scatter_kernel<<<(N_EDGES + 511) / 512, 512>>>(dst);

    seg_poly_kernel<<<N_EDGES / EPB, OP_SIZE>>>(x_nodes, x_edges, src, dst, out);
}

// round 12
// speedup vs baseline: 1.4616x; 1.4616x over previous
#include <cuda_runtime.h>
#include <cuda_fp16.h>

// Problem constants (fixed by the reference)
#define N_NODES 20000
#define N_EDGES 200000
#define N_SEG   16
#define EXTENT  32
#define N_PATHS 64
#define OP_SIZE (N_SEG * EXTENT)   // 512
#define EPB     8                  // edges per block (200000 % 8 == 0)

// Path metadata sorted by output segment (i3), built by prep kernel.
// meta.x = i1 tile byte offset in half[pos][EPB] layout (= i1*EXTENT*EPB*2)
// meta.y = i2 tile byte offset, meta.z = coeff bits (f32).
__device__ int4 g_meta[N_PATHS];
__device__ int  g_seg_start[N_SEG + 1];

__global__ void prep_paths_kernel(const int* __restrict__ path_indices,
                                  const float* __restrict__ path_coeffs) {
    if (threadIdx.x != 0 || blockIdx.x != 0) return;
    int cnt[N_SEG];
#pragma unroll
    for (int s = 0; s < N_SEG; s++) cnt[s] = 0;
    for (int p = 0; p < N_PATHS; p++) cnt[path_indices[p * 3 + 2]]++;
    int start[N_SEG + 1];
    start[0] = 0;
#pragma unroll
    for (int s = 0; s < N_SEG; s++) start[s + 1] = start[s] + cnt[s];
    for (int s = 0; s <= N_SEG; s++) g_seg_start[s] = start[s];
    int pos[N_SEG];
#pragma unroll
    for (int s = 0; s < N_SEG; s++) pos[s] = start[s];
    for (int p = 0; p < N_PATHS; p++) {
        int s   = path_indices[p * 3 + 2];
        int idx = pos[s]++;
        int4 m;
        m.x = path_indices[p * 3 + 0] * (EXTENT * EPB * 2);  // bytes
        m.y = path_indices[p * 3 + 1] * (EXTENT * EPB * 2);
        m.z = __float_as_int(path_coeffs[p]);
        m.w = 0;
        g_meta[idx] = m;
    }
}

// 8 edges per block (natural order -> x_edges stays a sequential stream),
// f16 tiles transposed to [pos][edge]: one LDS.128 fetches all 8 edges'
// values for a (seg,lane) position. 512 threads = 16 seg x 32 ext.
// x_edges loads use __ldcs (evict-first) so the 410MB stream doesn't thrash
// the L2-resident out / x_nodes working sets.
__global__ __launch_bounds__(OP_SIZE, 4)
void seg_poly_kernel(const float* __restrict__ x_nodes,
                     const float* __restrict__ x_edges,
                     const int* __restrict__ src,
                     const int* __restrict__ dst,
                     float* __restrict__ out) {
    __shared__ __align__(16) __half s_x1[OP_SIZE * EPB];  // 8 KB
    __shared__ __align__(16) __half s_x2[OP_SIZE * EPB];  // 8 KB
    __shared__ int4 s_meta[N_PATHS];
    __shared__ int  s_start[N_SEG + 1];
    __shared__ int  s_dst[EPB];

    const int e0 = blockIdx.x * EPB;
    const int t  = threadIdx.x;

    // Stage x_edges: thread t owns position t; gather from all 8 edges
    // (each LDG coalesced in-warp, 8 independent loads -> MLP 8), one STS.128.
    {
        const float* base = x_edges + (size_t)e0 * OP_SIZE + t;
        float v[EPB];
#pragma unroll
        for (int k = 0; k < EPB; k++)
            v[k] = __ldcs(base + k * OP_SIZE);          // streaming, evict-first
        __half2 h0 = __floats2half2_rn(v[0], v[1]);
        __half2 h1 = __floats2half2_rn(v[2], v[3]);
        __half2 h2 = __floats2half2_rn(v[4], v[5]);
        __half2 h3 = __floats2half2_rn(v[6], v[7]);
        uint4 pk;
        pk.x = *(const unsigned*)&h0; pk.y = *(const unsigned*)&h1;
        pk.z = *(const unsigned*)&h2; pk.w = *(const unsigned*)&h3;
        ((uint4*)s_x2)[t] = pk;   // addr = t*16 -> conflict-free
    }
    // Stage x_nodes rows src[e0..e0+7] (reused across edges -> default caching).
    {
        int r[EPB];
#pragma unroll
        for (int e = 0; e < EPB; e++) r[e] = src[e0 + e];
        float v[EPB];
#pragma unroll
        for (int e = 0; e < EPB; e++)
            v[e] = x_nodes[(size_t)r[e] * OP_SIZE + t];
        __half2 h0 = __floats2half2_rn(v[0], v[1]);
        __half2 h1 = __floats2half2_rn(v[2], v[3]);
        __half2 h2 = __floats2half2_rn(v[4], v[5]);
        __half2 h3 = __floats2half2_rn(v[6], v[7]);
        uint4 pk;
        pk.x = *(const unsigned*)&h0; pk.y = *(const unsigned*)&h1;
        pk.z = *(const unsigned*)&h2; pk.w = *(const unsigned*)&h3;
        ((uint4*)s_x1)[t] = pk;
    }

    if (t < N_PATHS) s_meta[t] = g_meta[t];
    if (t <= N_SEG)  s_start[t] = g_seg_start[t];
    if (t < EPB)     s_dst[t] = dst[e0 + t];
    __syncthreads();

    const int lane = t & 31;
    const int j0 = s_start[t >> 5];
    const int j1 = s_start[(t >> 5) + 1];

    const char* b1 = (const char*)s_x1 + lane * (EPB * 2);
    const char* b2 = (const char*)s_x2 + lane * (EPB * 2);

    float a0 = 0.f, a1 = 0.f, a2 = 0.f, a3 = 0.f;
    float a4 = 0.f, a5 = 0.f, a6 = 0.f, a7 = 0.f;

    for (int j = j0; j < j1; j++) {
        const int4 m = s_meta[j];                       // LDS.128, warp-uniform
        const float c = __int_as_float(m.z);
        const uint4 w1 = *(const uint4*)(b1 + m.x);     // LDS.128: 8 edges (x1)
        const uint4 w2 = *(const uint4*)(b2 + m.y);     // LDS.128: 8 edges (x2)
        const __half2 p0 = __hmul2(*(const __half2*)&w1.x, *(const __half2*)&w2.x);
        const __half2 p1 = __hmul2(*(const __half2*)&w1.y, *(const __half2*)&w2.y);
        const __half2 p2 = __hmul2(*(const __half2*)&w1.z, *(const __half2*)&w2.z);
        const __half2 p3 = __hmul2(*(const __half2*)&w1.w, *(const __half2*)&w2.w);
        const float2 f0 = __half22float2(p0);
        const float2 f1 = __half22float2(p1);
        const float2 f2 = __half22float2(p2);
        const float2 f3 = __half22float2(p3);
        a0 = fmaf(c, f0.x, a0);  a1 = fmaf(c, f0.y, a1);
        a2 = fmaf(c, f1.x, a2);  a3 = fmaf(c, f1.y, a3);
        a4 = fmaf(c, f2.x, a4);  a5 = fmaf(c, f2.y, a5);
        a6 = fmaf(c, f3.x, a6);  a7 = fmaf(c, f3.y, a7);
    }

    if (j1 > j0) {
        // Unused return -> no-return global reduction, coalesced 128B per warp.
        atomicAdd(&out[(size_t)s_dst[0] * OP_SIZE + t], a0);
        atomicAdd(&out[(size_t)s_dst[1] * OP_SIZE + t], a1);
        atomicAdd(&out[(size_t)s_dst[2] * OP_SIZE + t], a2);
        atomicAdd(&out[(size_t)s_dst[3] * OP_SIZE + t], a3);
        atomicAdd(&out[(size_t)s_dst[4] * OP_SIZE + t], a4);
        atomicAdd(&out[(size_t)s_dst[5] * OP_SIZE + t], a5);
        atomicAdd(&out[(size_t)s_dst[6] * OP_SIZE + t], a6);
        atomicAdd(&out[(size_t)s_dst[7] * OP_SIZE + t], a7);
    }
    // Segments with no paths contribute exactly 0 -> output stays at memset 0.
}

extern "C" void kernel_launch(void* const* d_in, const int* in_sizes, int n_in,
                              void* d_out, int out_size) {
    const float* x_nodes      = (const float*)d_in[0];
    const float* x_edges      = (const float*)d_in[1];
    const float* path_coeffs  = (const float*)d_in[2];
    const int*   src          = (const int*)d_in[3];
    const int*   dst          = (const int*)d_in[4];
    const int*   path_indices = (const int*)d_in[5];
    float* out = (float*)d_out;

    // Output is poisoned 0xAA by the harness; zero it (graph-capturable).
    cudaMemsetAsync(out, 0, (size_t)N_NODES * OP_SIZE * sizeof(float));

    prep_paths_kernel<<<1, 32>>>(path_indices, path_coeffs);

    seg_poly_kernel<<<N_EDGES / EPB, OP_SIZE>>>(x_nodes, x_edges, src, dst, out);
}

// round 13
// speedup vs baseline: 1.5847x; 1.0843x over previous
#include <cuda_runtime.h>
#include <cuda_fp16.h>

// Problem constants (fixed by the reference)
#define N_NODES 20000
#define N_EDGES 200000
#define N_SEG   16
#define EXTENT  32
#define N_PATHS 64
#define OP_SIZE (N_SEG * EXTENT)   // 512
#define EPB     8                  // edges per block (200000 % 8 == 0)

// Path metadata sorted by output segment (i3), built by prep kernel.
// meta.x = i1 tile byte offset in half[pos][EPB] layout (= i1*EXTENT*EPB*2)
// meta.y = i2 tile byte offset, meta.z = coeff bits (f32).
__device__ int4 g_meta[N_PATHS];
__device__ int  g_seg_start[N_SEG + 1];

__global__ void prep_paths_kernel(const int* __restrict__ path_indices,
                                  const float* __restrict__ path_coeffs) {
    if (threadIdx.x != 0 || blockIdx.x != 0) return;
    int cnt[N_SEG];
#pragma unroll
    for (int s = 0; s < N_SEG; s++) cnt[s] = 0;
    for (int p = 0; p < N_PATHS; p++) cnt[path_indices[p * 3 + 2]]++;
    int start[N_SEG + 1];
    start[0] = 0;
#pragma unroll
    for (int s = 0; s < N_SEG; s++) start[s + 1] = start[s] + cnt[s];
    for (int s = 0; s <= N_SEG; s++) g_seg_start[s] = start[s];
    int pos[N_SEG];
#pragma unroll
    for (int s = 0; s < N_SEG; s++) pos[s] = start[s];
    for (int p = 0; p < N_PATHS; p++) {
        int s   = path_indices[p * 3 + 2];
        int idx = pos[s]++;
        int4 m;
        m.x = path_indices[p * 3 + 0] * (EXTENT * EPB * 2);  // bytes
        m.y = path_indices[p * 3 + 1] * (EXTENT * EPB * 2);
        m.z = __float_as_int(path_coeffs[p]);
        m.w = 0;
        g_meta[idx] = m;
    }
}

// One iteration of the path contraction (8 edges), kept in a macro-like
// inline so the unrolled/predicated and spill loops share code.
__device__ __forceinline__ void path_step(const int4 m,
                                          const char* b1, const char* b2,
                                          float* a) {
    const float c = __int_as_float(m.z);
    const uint4 w1 = *(const uint4*)(b1 + m.x);     // LDS.128: 8 edges (x1)
    const uint4 w2 = *(const uint4*)(b2 + m.y);     // LDS.128: 8 edges (x2)
    const __half2 p0 = __hmul2(*(const __half2*)&w1.x, *(const __half2*)&w2.x);
    const __half2 p1 = __hmul2(*(const __half2*)&w1.y, *(const __half2*)&w2.y);
    const __half2 p2 = __hmul2(*(const __half2*)&w1.z, *(const __half2*)&w2.z);
    const __half2 p3 = __hmul2(*(const __half2*)&w1.w, *(const __half2*)&w2.w);
    const float2 f0 = __half22float2(p0);
    const float2 f1 = __half22float2(p1);
    const float2 f2 = __half22float2(p2);
    const float2 f3 = __half22float2(p3);
    a[0] = fmaf(c, f0.x, a[0]);  a[1] = fmaf(c, f0.y, a[1]);
    a[2] = fmaf(c, f1.x, a[2]);  a[3] = fmaf(c, f1.y, a[3]);
    a[4] = fmaf(c, f2.x, a[4]);  a[5] = fmaf(c, f2.y, a[5]);
    a[6] = fmaf(c, f3.x, a[6]);  a[7] = fmaf(c, f3.y, a[7]);
}

// 8 edges per block (natural order -> x_edges stays a sequential stream),
// f16 tiles transposed to [pos][edge]: one LDS.128 fetches all 8 edges'
// values for a (seg,lane) position. 512 threads = 16 seg x 32 ext.
__global__ __launch_bounds__(OP_SIZE, 4)
void seg_poly_kernel(const float* __restrict__ x_nodes,
                     const float* __restrict__ x_edges,
                     const int* __restrict__ src,
                     const int* __restrict__ dst,
                     float* __restrict__ out) {
    __shared__ __align__(16) __half s_x1[OP_SIZE * EPB];  // 8 KB
    __shared__ __align__(16) __half s_x2[OP_SIZE * EPB];  // 8 KB
    __shared__ int4 s_meta[N_PATHS];
    __shared__ int  s_start[N_SEG + 1];
    __shared__ int  s_dst[EPB];

    const int e0 = blockIdx.x * EPB;
    const int t  = threadIdx.x;

    // Stage x_edges: thread t owns position t; gather from all 8 edges
    // (each LDG coalesced in-warp, 8 independent loads -> MLP 8), one STS.128.
    {
        const float* base = x_edges + (unsigned)(e0 * OP_SIZE) + t;
        float v[EPB];
#pragma unroll
        for (int k = 0; k < EPB; k++)
            v[k] = __ldcs(base + k * OP_SIZE);          // streaming, evict-first
        __half2 h0 = __floats2half2_rn(v[0], v[1]);
        __half2 h1 = __floats2half2_rn(v[2], v[3]);
        __half2 h2 = __floats2half2_rn(v[4], v[5]);
        __half2 h3 = __floats2half2_rn(v[6], v[7]);
        uint4 pk;
        pk.x = *(const unsigned*)&h0; pk.y = *(const unsigned*)&h1;
        pk.z = *(const unsigned*)&h2; pk.w = *(const unsigned*)&h3;
        ((uint4*)s_x2)[t] = pk;   // addr = t*16 -> conflict-free
    }
    // Stage x_nodes rows src[e0..e0+7] (reused across edges -> default caching).
    // 32-bit offsets: max row offset = 20000*512 floats = 41MB, fits unsigned.
    {
        unsigned r[EPB];
#pragma unroll
        for (int e = 0; e < EPB; e++)
            r[e] = (unsigned)src[e0 + e] * (unsigned)OP_SIZE + (unsigned)t;
        float v[EPB];
#pragma unroll
        for (int e = 0; e < EPB; e++)
            v[e] = x_nodes[r[e]];
        __half2 h0 = __floats2half2_rn(v[0], v[1]);
        __half2 h1 = __floats2half2_rn(v[2], v[3]);
        __half2 h2 = __floats2half2_rn(v[4], v[5]);
        __half2 h3 = __floats2half2_rn(v[6], v[7]);
        uint4 pk;
        pk.x = *(const unsigned*)&h0; pk.y = *(const unsigned*)&h1;
        pk.z = *(const unsigned*)&h2; pk.w = *(const unsigned*)&h3;
        ((uint4*)s_x1)[t] = pk;
    }

    if (t < N_PATHS) s_meta[t] = g_meta[t];
    if (t <= N_SEG)  s_start[t] = g_seg_start[t];
    if (t < EPB)     s_dst[t] = dst[e0 + t];
    __syncthreads();

    const int lane = t & 31;
    const int j0 = s_start[t >> 5];
    const int j1 = s_start[(t >> 5) + 1];

    const char* b1 = (const char*)s_x1 + lane * (EPB * 2);
    const char* b2 = (const char*)s_x2 + lane * (EPB * 2);

    float a[EPB];
#pragma unroll
    for (int k = 0; k < EPB; k++) a[k] = 0.f;

    // Guarded unroll-4 (covers most segments; ~4 paths avg per segment):
    // predication lets ptxas batch the LDS.128s of all 4 iterations -> MLP.
#pragma unroll
    for (int u = 0; u < 4; u++) {
        const int j = j0 + u;
        if (j < j1) path_step(s_meta[j], b1, b2, a);
    }
    // Spill for segments with >4 paths (rare).
    for (int j = j0 + 4; j < j1; j++) path_step(s_meta[j], b1, b2, a);

    if (j1 > j0) {
        // Unused return -> no-return global reduction, coalesced 128B per warp.
        float* obase = out + t;
#pragma unroll
        for (int k = 0; k < EPB; k++)
            atomicAdd(obase + (unsigned)s_dst[k] * (unsigned)OP_SIZE, a[k]);
    }
    // Segments with no paths contribute exactly 0 -> output stays at memset 0.
}

extern "C" void kernel_launch(void* const* d_in, const int* in_sizes, int n_in,
                              void* d_out, int out_size) {
    const float* x_nodes      = (const float*)d_in[0];
    const float* x_edges      = (const float*)d_in[1];
    const float* path_coeffs  = (const float*)d_in[2];
    const int*   src          = (const int*)d_in[3];
    const int*   dst          = (const int*)d_in[4];
    const int*   path_indices = (const int*)d_in[5];
    float* out = (float*)d_out;

    // Output is poisoned 0xAA by the harness; zero it (graph-capturable).
    cudaMemsetAsync(out, 0, (size_t)N_NODES * OP_SIZE * sizeof(float));

    prep_paths_kernel<<<1, 32>>>(path_indices, path_coeffs);

    seg_poly_kernel<<<N_EDGES / EPB, OP_SIZE>>>(x_nodes, x_edges, src, dst, out);
}

// round 15
// speedup vs baseline: 1.5958x; 1.0070x over previous
#include <cuda_runtime.h>
#include <cuda_fp16.h>

// Problem constants (fixed by the reference)
#define N_NODES 20000
#define N_EDGES 200000
#define N_SEG   16
#define EXTENT  32
#define N_PATHS 64
#define OP_SIZE (N_SEG * EXTENT)   // 512
#define EPB     8                  // edges per group
#define GPB     2                  // groups per block (pipelined)
#define OUT_ELEMS (N_NODES * OP_SIZE)

// Path metadata sorted by output segment (i3), built by prep kernel.
// meta.x = i1 tile byte offset in half[pos][EPB] layout (= i1*EXTENT*EPB*2)
// meta.y = i2 tile byte offset, meta.z = coeff bits (f32).
__device__ int4 g_meta[N_PATHS];
__device__ int  g_seg_start[N_SEG + 1];

// Prep: grid-stride zero of out (harness poisons it) + single-thread path sort.
__global__ void prep_kernel(const int* __restrict__ path_indices,
                            const float* __restrict__ path_coeffs,
                            float4* __restrict__ out4) {
    const int i = blockIdx.x * blockDim.x + threadIdx.x;
    const int stride = gridDim.x * blockDim.x;
    for (int k = i; k < OUT_ELEMS / 4; k += stride)
        out4[k] = make_float4(0.f, 0.f, 0.f, 0.f);

    if (blockIdx.x == 0 && threadIdx.x == 0) {
        int cnt[N_SEG];
#pragma unroll
        for (int s = 0; s < N_SEG; s++) cnt[s] = 0;
        for (int p = 0; p < N_PATHS; p++) cnt[path_indices[p * 3 + 2]]++;
        int start[N_SEG + 1];
        start[0] = 0;
#pragma unroll
        for (int s = 0; s < N_SEG; s++) start[s + 1] = start[s] + cnt[s];
        for (int s = 0; s <= N_SEG; s++) g_seg_start[s] = start[s];
        int pos[N_SEG];
#pragma unroll
        for (int s = 0; s < N_SEG; s++) pos[s] = start[s];
        for (int p = 0; p < N_PATHS; p++) {
            int s   = path_indices[p * 3 + 2];
            int idx = pos[s]++;
            int4 m;
            m.x = path_indices[p * 3 + 0] * (EXTENT * EPB * 2);  // bytes
            m.y = path_indices[p * 3 + 1] * (EXTENT * EPB * 2);
            m.z = __float_as_int(path_coeffs[p]);
            m.w = 0;
            g_meta[idx] = m;
        }
    }
}

// Stage one 8-edge group into the given f16 tile pair ([pos][edge] transposed).
__device__ __forceinline__ void stage_group(const float* __restrict__ x_nodes,
                                            const float* __restrict__ x_edges,
                                            const int* __restrict__ src,
                                            int e0, int t,
                                            __half* s_x1, __half* s_x2) {
    // x_edges: thread t owns position t; gather from 8 edges (MLP 8), evict-first.
    {
        const float* base = x_edges + (size_t)e0 * OP_SIZE + t;
        float v[EPB];
#pragma unroll
        for (int k = 0; k < EPB; k++)
            v[k] = __ldcs(base + k * OP_SIZE);
        __half2 h0 = __floats2half2_rn(v[0], v[1]);
        __half2 h1 = __floats2half2_rn(v[2], v[3]);
        __half2 h2 = __floats2half2_rn(v[4], v[5]);
        __half2 h3 = __floats2half2_rn(v[6], v[7]);
        uint4 pk;
        pk.x = *(const unsigned*)&h0; pk.y = *(const unsigned*)&h1;
        pk.z = *(const unsigned*)&h2; pk.w = *(const unsigned*)&h3;
        ((uint4*)s_x2)[t] = pk;   // addr = t*16 -> conflict-free
    }
    // x_nodes rows src[e0..e0+7]; 32-bit offsets (41MB fits unsigned).
    {
        unsigned r[EPB];
#pragma unroll
        for (int e = 0; e < EPB; e++)
            r[e] = (unsigned)src[e0 + e] * (unsigned)OP_SIZE + (unsigned)t;
        float v[EPB];
#pragma unroll
        for (int e = 0; e < EPB; e++)
            v[e] = x_nodes[r[e]];
        __half2 h0 = __floats2half2_rn(v[0], v[1]);
        __half2 h1 = __floats2half2_rn(v[2], v[3]);
        __half2 h2 = __floats2half2_rn(v[4], v[5]);
        __half2 h3 = __floats2half2_rn(v[6], v[7]);
        uint4 pk;
        pk.x = *(const unsigned*)&h0; pk.y = *(const unsigned*)&h1;
        pk.z = *(const unsigned*)&h2; pk.w = *(const unsigned*)&h3;
        ((uint4*)s_x1)[t] = pk;
    }
}

// One path-contraction step over 8 edges.
__device__ __forceinline__ void path_step(const int4 m,
                                          const char* b1, const char* b2,
                                          float* a) {
    const float c = __int_as_float(m.z);
    const uint4 w1 = *(const uint4*)(b1 + m.x);     // LDS.128: 8 edges (x1)
    const uint4 w2 = *(const uint4*)(b2 + m.y);     // LDS.128: 8 edges (x2)
    const __half2 p0 = __hmul2(*(const __half2*)&w1.x, *(const __half2*)&w2.x);
    const __half2 p1 = __hmul2(*(const __half2*)&w1.y, *(const __half2*)&w2.y);
    const __half2 p2 = __hmul2(*(const __half2*)&w1.z, *(const __half2*)&w2.z);
    const __half2 p3 = __hmul2(*(const __half2*)&w1.w, *(const __half2*)&w2.w);
    const float2 f0 = __half22float2(p0);
    const float2 f1 = __half22float2(p1);
    const float2 f2 = __half22float2(p2);
    const float2 f3 = __half22float2(p3);
    a[0] = fmaf(c, f0.x, a[0]);  a[1] = fmaf(c, f0.y, a[1]);
    a[2] = fmaf(c, f1.x, a[2]);  a[3] = fmaf(c, f1.y, a[3]);
    a[4] = fmaf(c, f2.x, a[4]);  a[5] = fmaf(c, f2.y, a[5]);
    a[6] = fmaf(c, f3.x, a[6]);  a[7] = fmaf(c, f3.y, a[7]);
}

// Two pipelined 8-edge groups per block, double-buffered f16 tiles.
// Per warp: stage0 -> bar -> compute0 -> atomics0 -> stage1(buf1) -> bar ->
// compute1 -> atomics1.  Group 1's LDG latency hides behind other warps'
// compute/atomics instead of an SM-wide barrier bubble.
__global__ __launch_bounds__(OP_SIZE, 4)
void seg_poly_kernel(const float* __restrict__ x_nodes,
                     const float* __restrict__ x_edges,
                     const int* __restrict__ src,
                     const int* __restrict__ dst,
                     float* __restrict__ out) {
    __shared__ __align__(16) __half s_x1[GPB][OP_SIZE * EPB];  // 2 x 8 KB
    __shared__ __align__(16) __half s_x2[GPB][OP_SIZE * EPB];  // 2 x 8 KB
    __shared__ int4 s_meta[N_PATHS];
    __shared__ int  s_start[N_SEG + 1];
    __shared__ int  s_dst[GPB][EPB];

    const int e0 = blockIdx.x * (GPB * EPB);
    const int t  = threadIdx.x;

    stage_group(x_nodes, x_edges, src, e0, t, s_x1[0], s_x2[0]);

    if (t < N_PATHS) s_meta[t] = g_meta[t];
    if (t <= N_SEG)  s_start[t] = g_seg_start[t];
    if (t < GPB * EPB) s_dst[t / EPB][t % EPB] = dst[e0 + t];
    __syncthreads();

    const int lane = t & 31;
    const int j0 = s_start[t >> 5];
    const int j1 = s_start[(t >> 5) + 1];
    const int loff = lane * (EPB * 2);

#pragma unroll
    for (int g = 0; g < GPB; g++) {
        const char* b1 = (const char*)s_x1[g] + loff;
        const char* b2 = (const char*)s_x2[g] + loff;

        float a[EPB];
#pragma unroll
        for (int k = 0; k < EPB; k++) a[k] = 0.f;

        // Guarded unroll-4 (most segments have <=4 paths) + rare spill.
#pragma unroll
        for (int u = 0; u < 4; u++) {
            const int j = j0 + u;
            if (j < j1) path_step(s_meta[j], b1, b2, a);
        }
        for (int j = j0 + 4; j < j1; j++) path_step(s_meta[j], b1, b2, a);

        if (j1 > j0) {
            // Unused return -> no-return reduction, coalesced 128B per warp.
            float* obase = out + t;
#pragma unroll
            for (int k = 0; k < EPB; k++)
                atomicAdd(obase + (unsigned)s_dst[g][k] * (unsigned)OP_SIZE, a[k]);
        }

        if (g + 1 < GPB) {
            // Pre-barrier staging of the next group into the other buffer:
            // LDG latency overlaps other warps' compute/atomics of group g.
            stage_group(x_nodes, x_edges, src, e0 + (g + 1) * EPB, t,
                        s_x1[g + 1], s_x2[g + 1]);
            __syncthreads();
        }
    }
    // Segments with no paths contribute exactly 0 -> output stays zeroed.
}

extern "C" void kernel_launch(void* const* d_in, const int* in_sizes, int n_in,
                              void* d_out, int out_size) {
    const float* x_nodes      = (const float*)d_in[0];
    const float* x_edges      = (const float*)d_in[1];
    const float* path_coeffs  = (const float*)d_in[2];
    const int*   src          = (const int*)d_in[3];
    const int*   dst          = (const int*)d_in[4];
    const int*   path_indices = (const int*)d_in[5];
    float* out = (float*)d_out;

    // Zero the poisoned output + build path metadata in one launch.
    prep_kernel<<<2048, 256>>>(path_indices, path_coeffs, (float4*)out);

    seg_poly_kernel<<<N_EDGES / (GPB * EPB), OP_SIZE>>>(x_nodes, x_edges,
                                                        src, dst, out);
}